// round 1
// baseline (speedup 1.0000x reference)
#include <cuda_runtime.h>
#include <math.h>

#define D_ 128
#define H_ 256
#define N_ 4
#define V_ 100
#define B_ 64
#define S_ 2048

// ---- Transposed weights (column-major: [k][out]) in device globals (L2-resident) ----
__device__ __align__(16) float g_WihT[128 * 3072];   // [k][n*768+g]
__device__ __align__(16) float g_WhhT[256 * 1536];   // [k][m*768+g]  (compute neurons 2,3)
__device__ __align__(16) float g_WopT[256 * 512];    // [k][n*128+d]
__device__ __align__(16) float g_WqT [128 * 128];    // [k][d]
__device__ __align__(16) float g_WkT [128 * 128];
__device__ __align__(16) float g_WvT [128 * 128];
__device__ __align__(16) float g_Wf1T[128 * 128];
__device__ __align__(16) float g_Wf2T[128 * 128];
__device__ __align__(16) float g_WwoT[128 * 128];
__device__ __align__(16) float g_WfbT[128 * 128];
__device__ __align__(16) float g_WrT [512 * 100];    // [k][v]

__global__ void prep_kernel(const float* __restrict__ W_ih, const float* __restrict__ W_hh_c,
                            const float* __restrict__ W_op, const float* __restrict__ Wq,
                            const float* __restrict__ Wk,   const float* __restrict__ Wv,
                            const float* __restrict__ Wf1,  const float* __restrict__ Wf2,
                            const float* __restrict__ Wwo,  const float* __restrict__ Wfb,
                            const float* __restrict__ Wr)
{
    int i  = blockIdx.x * blockDim.x + threadIdx.x;
    int st = gridDim.x * blockDim.x;
    for (int p = i; p < 128 * 3072; p += st) { int k = p / 3072, o = p - k * 3072; g_WihT[p] = W_ih[o * 128 + k]; }
    for (int p = i; p < 256 * 1536; p += st) { int k = p / 1536, o = p - k * 1536; g_WhhT[p] = W_hh_c[o * 256 + k]; }
    for (int p = i; p < 256 * 512;  p += st) { int k = p >> 9,  o = p & 511;       g_WopT[p] = W_op[o * 256 + k]; }
    for (int p = i; p < 128 * 128;  p += st) {
        int k = p >> 7, d = p & 127;
        g_WqT [p] = Wq [d * 128 + k]; g_WkT [p] = Wk [d * 128 + k]; g_WvT [p] = Wv [d * 128 + k];
        g_Wf1T[p] = Wf1[d * 128 + k]; g_Wf2T[p] = Wf2[d * 128 + k]; g_WwoT[p] = Wwo[d * 128 + k];
        g_WfbT[p] = Wfb[d * 128 + k];
    }
    for (int p = i; p < 512 * 100; p += st) { int k = p / 100, v = p - k * 100; g_WrT[p] = Wr[v * 512 + k]; }
}

__device__ __forceinline__ void fma4(float4& a, const float4 w, const float x) {
    a.x = fmaf(w.x, x, a.x); a.y = fmaf(w.y, x, a.y);
    a.z = fmaf(w.z, x, a.z); a.w = fmaf(w.w, x, a.w);
}
__device__ __forceinline__ float sigf(float x) { return 1.0f / (1.0f + expf(-x)); }
__device__ __forceinline__ float geluf(float x) { return 0.5f * x * (1.0f + erff(x * 0.7071067811865475f)); }

__global__ void __launch_bounds__(512, 1)
inn_kernel(const int* __restrict__ x, const float* __restrict__ emb,
           const float* __restrict__ b_ih, const float* __restrict__ b_hh_c,
           const float* __restrict__ b_op,
           const float* __restrict__ bq, const float* __restrict__ bk, const float* __restrict__ bv,
           const float* __restrict__ bf1, const float* __restrict__ bf2, const float* __restrict__ bwo,
           const float* __restrict__ gamma, const float* __restrict__ beta,
           const float* __restrict__ br, const float* __restrict__ bfb,
           float* __restrict__ out, int write_states)
{
    const int b = blockIdx.x;
    const int t = threadIdx.x;

    __shared__ __align__(16) float sh_h[4 * 256];
    __shared__ __align__(16) float sh_fb[128];
    __shared__ __align__(16) float sh_c[128];
    __shared__ __align__(16) float sh_gi[3072];      // also reused as K-split scratch
    __shared__ __align__(16) float sh_gh[1536];
    __shared__ __align__(16) float sh_o[512];
    __shared__ __align__(16) float sh_q[512];
    __shared__ __align__(16) float sh_k[512];
    __shared__ __align__(16) float sh_v[512];
    __shared__ float sh_sc[16];
    __shared__ __align__(16) float sh_mx[512];
    __shared__ __align__(16) float sh_g1[512];
    __shared__ __align__(16) float sh_pc[512];
    __shared__ __align__(16) float sh_rs[512];
    __shared__ __align__(16) float sh_on[512];
    __shared__ float sh_red[32];
    __shared__ float sh_mu[4], sh_rstd[4];
    __shared__ __align__(16) float sh_part[512];

    for (int j = t; j < 1024; j += 512) sh_h[j] = 0.0f;
    if (t < 128) sh_fb[t] = 0.0f;
    __syncthreads();

    const float inv_sqrt_d = 0.08838834764831845f;  // 1/sqrt(128)

    for (int s = 0; s < S_; ++s) {
        // ---------- Stage A: c = emb[tok] + fb @ Wfb^T + bfb ----------
        const int tok = x[b * S_ + s];
        const float* e = emb + (size_t)tok * D_;
        {
            int d = t & 127, g = t >> 7;
            float acc = 0.0f;
            #pragma unroll 8
            for (int k = g * 32; k < g * 32 + 32; ++k)
                acc = fmaf(g_WfbT[k * 128 + d], sh_fb[k], acc);
            sh_part[g * 128 + d] = acc;
        }
        __syncthreads();
        if (t < 128)
            sh_c[t] = e[t] + bfb[t] + sh_part[t] + sh_part[128 + t] + sh_part[256 + t] + sh_part[384 + t];
        __syncthreads();

        // ---------- Stage B: gi[n,3H] = W_ih @ c + b_ih  (3072 outs, 768 f4 groups) ----------
        #pragma unroll
        for (int r = 0; r < 2; ++r) {
            int grp = t + r * 512;
            if (grp < 768) {
                float4 acc = *(const float4*)(b_ih + grp * 4);
                #pragma unroll 4
                for (int k = 0; k < 128; ++k) {
                    float xk = sh_c[k];
                    float4 w = *(const float4*)(g_WihT + (size_t)k * 3072 + grp * 4);
                    fma4(acc, w, xk);
                }
                *(float4*)(sh_gi + grp * 4) = acc;
            }
        }
        // ---------- Stage C: gh for compute neurons 2,3 (1536 outs, 384 f4 groups) ----------
        if (t < 384) {
            int grp = t;
            int m = grp / 192;                       // 0 or 1, warp-uniform (192 % 32 == 0)
            const float* hrow = sh_h + (2 + m) * 256;
            float4 acc = *(const float4*)(b_hh_c + grp * 4);
            #pragma unroll 4
            for (int k = 0; k < 256; ++k) {
                float hk = hrow[k];
                float4 w = *(const float4*)(g_WhhT + (size_t)k * 1536 + grp * 4);
                fma4(acc, w, hk);
            }
            *(float4*)(sh_gh + grp * 4) = acc;
        }
        __syncthreads();

        // ---------- Stage D: GRU gates + h update (1024 elems) ----------
        #pragma unroll
        for (int r = 0; r < 2; ++r) {
            int j = t + r * 512;
            int n = j >> 8, hi = j & 255;
            float h_old = sh_h[n * 256 + hi];
            float gir = sh_gi[n * 768 + hi];
            float giz = sh_gi[n * 768 + 256 + hi];
            float gin = sh_gi[n * 768 + 512 + hi];
            float ghr, ghz, ghn;
            if (n < 2) { ghr = 0.0f; ghz = 5.0f; ghn = h_old; }            // locked neuron
            else {
                int mm = n - 2;
                ghr = sh_gh[mm * 768 + hi];
                ghz = sh_gh[mm * 768 + 256 + hi];
                ghn = sh_gh[mm * 768 + 512 + hi];
            }
            float rg = sigf(gir + ghr);
            float zg = sigf(giz + ghz);
            float ng = tanhf(fmaf(rg, ghn, gin));
            sh_h[n * 256 + hi] = (1.0f - zg) * ng + zg * h_old;
        }
        __syncthreads();

        // ---------- Stage E: o = W_op @ hn + b_op (512 outs), K-split 4 over 256 ----------
        {
            int g = t & 127, ks = t >> 7;
            int n = g >> 5;
            const float* hrow = sh_h + n * 256;
            float4 acc = make_float4(0.f, 0.f, 0.f, 0.f);
            #pragma unroll 4
            for (int k = ks * 64; k < ks * 64 + 64; ++k) {
                float hk = hrow[k];
                float4 w = *(const float4*)(g_WopT + (size_t)k * 512 + g * 4);
                fma4(acc, w, hk);
            }
            *(float4*)(sh_gi + ks * 512 + g * 4) = acc;   // scratch
        }
        __syncthreads();
        if (t < 128) {
            float4 a0 = *(const float4*)(sh_gi + t * 4);
            float4 a1 = *(const float4*)(sh_gi + 512 + t * 4);
            float4 a2 = *(const float4*)(sh_gi + 1024 + t * 4);
            float4 a3 = *(const float4*)(sh_gi + 1536 + t * 4);
            float4 bo = *(const float4*)(b_op + t * 4);
            float4 r;
            r.x = a0.x + a1.x + a2.x + a3.x + bo.x;
            r.y = a0.y + a1.y + a2.y + a3.y + bo.y;
            r.z = a0.z + a1.z + a2.z + a3.z + bo.z;
            r.w = a0.w + a1.w + a2.w + a3.w + bo.w;
            *(float4*)(sh_o + t * 4) = r;
        }
        __syncthreads();

        // ---------- Stage F: q,k,v = o @ W^T + b  (3 x 512 outs) ----------
        if (t < 384) {
            int sel = t >> 7, g = t & 127;
            int n = g >> 5, d4 = g & 31;
            const float* xrow = sh_o + n * 128;
            const float* WT = (sel == 0) ? g_WqT : (sel == 1) ? g_WkT : g_WvT;
            const float* bb = (sel == 0) ? bq : (sel == 1) ? bk : bv;
            float4 acc = *(const float4*)(bb + d4 * 4);
            #pragma unroll 4
            for (int k = 0; k < 128; ++k) {
                float xk = xrow[k];
                float4 w = *(const float4*)(WT + k * 128 + d4 * 4);
                fma4(acc, w, xk);
            }
            float* dst = (sel == 0) ? sh_q : (sel == 1) ? sh_k : sh_v;
            *(float4*)(dst + g * 4) = acc;
        }
        __syncthreads();

        // ---------- Stage G: scores + softmax (N=4) ----------
        {
            int w = t >> 5, l = t & 31;
            int n = w >> 2, m = w & 3;
            float sum = sh_q[n * 128 + l]       * sh_k[m * 128 + l]
                      + sh_q[n * 128 + 32 + l]  * sh_k[m * 128 + 32 + l]
                      + sh_q[n * 128 + 64 + l]  * sh_k[m * 128 + 64 + l]
                      + sh_q[n * 128 + 96 + l]  * sh_k[m * 128 + 96 + l];
            #pragma unroll
            for (int off = 16; off; off >>= 1) sum += __shfl_down_sync(0xffffffff, sum, off);
            if (l == 0) sh_sc[n * 4 + m] = sum * inv_sqrt_d;
        }
        __syncthreads();
        if (t < 4) {
            float s0 = sh_sc[t * 4], s1 = sh_sc[t * 4 + 1], s2 = sh_sc[t * 4 + 2], s3 = sh_sc[t * 4 + 3];
            float mx = fmaxf(fmaxf(s0, s1), fmaxf(s2, s3));
            float e0 = expf(s0 - mx), e1 = expf(s1 - mx), e2 = expf(s2 - mx), e3 = expf(s3 - mx);
            float den = 1.0f / (e0 + e1 + e2 + e3);
            sh_sc[t * 4] = e0 * den; sh_sc[t * 4 + 1] = e1 * den;
            sh_sc[t * 4 + 2] = e2 * den; sh_sc[t * 4 + 3] = e3 * den;
        }
        __syncthreads();

        // ---------- Stage H: mixed = attn @ v ----------
        {
            int n = t >> 7, d = t & 127;
            sh_mx[t] = sh_sc[n * 4] * sh_v[d] + sh_sc[n * 4 + 1] * sh_v[128 + d]
                     + sh_sc[n * 4 + 2] * sh_v[256 + d] + sh_sc[n * 4 + 3] * sh_v[384 + d];
        }
        __syncthreads();

        // ---------- Stage I: f1 + exact GELU (K-split 4 over 128) ----------
        {
            int g = t & 127, ks = t >> 7;
            int n = g >> 5, d4 = g & 31;
            const float* xrow = sh_mx + n * 128;
            float4 acc = make_float4(0.f, 0.f, 0.f, 0.f);
            #pragma unroll 4
            for (int k = ks * 32; k < ks * 32 + 32; ++k) {
                float xk = xrow[k];
                float4 w = *(const float4*)(g_Wf1T + k * 128 + d4 * 4);
                fma4(acc, w, xk);
            }
            *(float4*)(sh_gi + ks * 512 + g * 4) = acc;
        }
        __syncthreads();
        if (t < 128) {
            int d4 = t & 31;
            float4 a0 = *(const float4*)(sh_gi + t * 4);
            float4 a1 = *(const float4*)(sh_gi + 512 + t * 4);
            float4 a2 = *(const float4*)(sh_gi + 1024 + t * 4);
            float4 a3 = *(const float4*)(sh_gi + 1536 + t * 4);
            float4 bb = *(const float4*)(bf1 + d4 * 4);
            float4 r;
            r.x = geluf(a0.x + a1.x + a2.x + a3.x + bb.x);
            r.y = geluf(a0.y + a1.y + a2.y + a3.y + bb.y);
            r.z = geluf(a0.z + a1.z + a2.z + a3.z + bb.z);
            r.w = geluf(a0.w + a1.w + a2.w + a3.w + bb.w);
            *(float4*)(sh_g1 + t * 4) = r;
        }
        __syncthreads();

        // ---------- Stage J: proc = g1 @ Wf2^T + bf2 ----------
        {
            int g = t & 127, ks = t >> 7;
            int n = g >> 5, d4 = g & 31;
            const float* xrow = sh_g1 + n * 128;
            float4 acc = make_float4(0.f, 0.f, 0.f, 0.f);
            #pragma unroll 4
            for (int k = ks * 32; k < ks * 32 + 32; ++k) {
                float xk = xrow[k];
                float4 w = *(const float4*)(g_Wf2T + k * 128 + d4 * 4);
                fma4(acc, w, xk);
            }
            *(float4*)(sh_gi + ks * 512 + g * 4) = acc;
        }
        __syncthreads();
        if (t < 128) {
            int d4 = t & 31;
            float4 a0 = *(const float4*)(sh_gi + t * 4);
            float4 a1 = *(const float4*)(sh_gi + 512 + t * 4);
            float4 a2 = *(const float4*)(sh_gi + 1024 + t * 4);
            float4 a3 = *(const float4*)(sh_gi + 1536 + t * 4);
            float4 bb = *(const float4*)(bf2 + d4 * 4);
            float4 r;
            r.x = a0.x + a1.x + a2.x + a3.x + bb.x;
            r.y = a0.y + a1.y + a2.y + a3.y + bb.y;
            r.z = a0.z + a1.z + a2.z + a3.z + bb.z;
            r.w = a0.w + a1.w + a2.w + a3.w + bb.w;
            *(float4*)(sh_pc + t * 4) = r;
        }
        __syncthreads();

        // ---------- Stage K: res = o + proc @ Wwo^T + bwo ; fb_next = mean_n proc ----------
        {
            int g = t & 127, ks = t >> 7;
            int n = g >> 5, d4 = g & 31;
            const float* xrow = sh_pc + n * 128;
            float4 acc = make_float4(0.f, 0.f, 0.f, 0.f);
            #pragma unroll 4
            for (int k = ks * 32; k < ks * 32 + 32; ++k) {
                float xk = xrow[k];
                float4 w = *(const float4*)(g_WwoT + k * 128 + d4 * 4);
                fma4(acc, w, xk);
            }
            *(float4*)(sh_gi + ks * 512 + g * 4) = acc;
        }
        __syncthreads();
        if (t < 128) {
            int d4 = t & 31;
            float4 a0 = *(const float4*)(sh_gi + t * 4);
            float4 a1 = *(const float4*)(sh_gi + 512 + t * 4);
            float4 a2 = *(const float4*)(sh_gi + 1024 + t * 4);
            float4 a3 = *(const float4*)(sh_gi + 1536 + t * 4);
            float4 bb = *(const float4*)(bwo + d4 * 4);
            float4 oo = *(const float4*)(sh_o + t * 4);
            float4 r;
            r.x = oo.x + a0.x + a1.x + a2.x + a3.x + bb.x;
            r.y = oo.y + a0.y + a1.y + a2.y + a3.y + bb.y;
            r.z = oo.z + a0.z + a1.z + a2.z + a3.z + bb.z;
            r.w = oo.w + a0.w + a1.w + a2.w + a3.w + bb.w;
            *(float4*)(sh_rs + t * 4) = r;
            // gvec -> feedback for next step
            sh_fb[t] = 0.25f * (sh_pc[t] + sh_pc[128 + t] + sh_pc[256 + t] + sh_pc[384 + t]);
        }
        __syncthreads();

        // ---------- Stage L: LayerNorm over D per (n) ----------
        {
            float v = sh_rs[t];
            float sum = v, sq = v * v;
            #pragma unroll
            for (int off = 16; off; off >>= 1) {
                sum += __shfl_down_sync(0xffffffff, sum, off);
                sq  += __shfl_down_sync(0xffffffff, sq,  off);
            }
            if ((t & 31) == 0) { sh_red[(t >> 5) * 2] = sum; sh_red[(t >> 5) * 2 + 1] = sq; }
        }
        __syncthreads();
        if (t < 4) {
            float sum = 0.f, sq = 0.f;
            #pragma unroll
            for (int w = t * 4; w < t * 4 + 4; ++w) { sum += sh_red[w * 2]; sq += sh_red[w * 2 + 1]; }
            float mu = sum * (1.0f / 128.0f);
            float var = sq * (1.0f / 128.0f) - mu * mu;
            sh_mu[t] = mu;
            sh_rstd[t] = rsqrtf(var + 1e-5f);
        }
        __syncthreads();
        {
            int n = t >> 7, d = t & 127;
            sh_on[t] = (sh_rs[t] - sh_mu[n]) * sh_rstd[n] * gamma[d] + beta[d];
        }
        __syncthreads();

        // ---------- Stage M: logits = outn_flat @ Wr^T + br ----------
        {
            int g2 = t >> 7, v = t & 127;
            float acc = 0.0f;
            if (v < 100) {
                #pragma unroll 4
                for (int k = g2 * 128; k < g2 * 128 + 128; ++k)
                    acc = fmaf(g_WrT[k * 100 + v], sh_on[k], acc);
            }
            sh_part[g2 * 128 + v] = acc;
        }
        __syncthreads();
        if (t < 100)
            out[(size_t)b * S_ * V_ + (size_t)s * V_ + t] =
                sh_part[t] + sh_part[128 + t] + sh_part[256 + t] + sh_part[384 + t] + br[t];
        __syncthreads();
    }

    // ---------- Final states: hF [N,B,H], fbF [B,D] ----------
    if (write_states) {
        size_t OFF1 = (size_t)B_ * S_ * V_;
        for (int j = t; j < 1024; j += 512) {
            int n = j >> 8, k = j & 255;
            out[OFF1 + (size_t)n * B_ * H_ + (size_t)b * H_ + k] = sh_h[j];
        }
        if (t < 128)
            out[OFF1 + (size_t)N_ * B_ * H_ + (size_t)b * D_ + t] = sh_fb[t];
    }
}

extern "C" void kernel_launch(void* const* d_in, const int* in_sizes, int n_in,
                              void* d_out, int out_size)
{
    const int*   x      = (const int*)  d_in[0];
    const float* emb    = (const float*)d_in[1];
    const float* W_ih   = (const float*)d_in[2];
    const float* b_ih   = (const float*)d_in[3];
    const float* W_hh_c = (const float*)d_in[4];
    const float* b_hh_c = (const float*)d_in[5];
    const float* W_op   = (const float*)d_in[6];
    const float* b_op   = (const float*)d_in[7];
    const float* Wq     = (const float*)d_in[8];
    const float* bq     = (const float*)d_in[9];
    const float* Wk     = (const float*)d_in[10];
    const float* bk     = (const float*)d_in[11];
    const float* Wv     = (const float*)d_in[12];
    const float* bv     = (const float*)d_in[13];
    const float* Wf1    = (const float*)d_in[14];
    const float* bf1    = (const float*)d_in[15];
    const float* Wf2    = (const float*)d_in[16];
    const float* bf2    = (const float*)d_in[17];
    const float* Wwo    = (const float*)d_in[18];
    const float* bwo    = (const float*)d_in[19];
    const float* gamma  = (const float*)d_in[20];
    const float* beta   = (const float*)d_in[21];
    const float* Wr     = (const float*)d_in[22];
    const float* br     = (const float*)d_in[23];
    const float* Wfb    = (const float*)d_in[24];
    const float* bfb    = (const float*)d_in[25];
    float* out = (float*)d_out;

    prep_kernel<<<512, 256>>>(W_ih, W_hh_c, W_op, Wq, Wk, Wv, Wf1, Wf2, Wwo, Wfb, Wr);

    long long FULL = (long long)B_ * S_ * V_ + (long long)N_ * B_ * H_ + (long long)B_ * D_;
    int write_states = ((long long)out_size >= FULL) ? 1 : 0;

    inn_kernel<<<B_, 512>>>(x, emb, b_ih, b_hh_c, b_op, bq, bk, bv, bf1, bf2, bwo,
                            gamma, beta, br, bfb, out, write_states);
}

// round 2
// speedup vs baseline: 2.0968x; 2.0968x over previous
#include <cuda_runtime.h>
#include <math.h>

#define D_ 128
#define H_ 256
#define N_ 4
#define V_ 100
#define B_ 64
#define S_ 2048

// ---- Device-global weights (transposed, column-major [k][out]) ----
__device__ __align__(16) float g_WihT[128 * 3072];   // for prep only
__device__ __align__(16) float g_WhhT[256 * 1536];
__device__ __align__(16) float g_WopT[256 * 512];
__device__ __align__(16) float g_WqT [128 * 128];
__device__ __align__(16) float g_WkT [128 * 128];
__device__ __align__(16) float g_WvT [128 * 128];
__device__ __align__(16) float g_Wf1T[128 * 128];
__device__ __align__(16) float g_Wf2T[128 * 128];
__device__ __align__(16) float g_WwoT[128 * 128];
__device__ __align__(16) float g_WrT [512 * 100];
__device__ __align__(16) float g_tab [100 * 3072];   // gi table: W_ih@(emb[v]+bfb) + b_ih
__device__ __align__(16) float g_McT [128 * 3072];   // (W_ih@Wfb^T) transposed, fallback only
__device__ int g_fb_active;

// ---------------- f32x2 packed helpers ----------------
__device__ __forceinline__ void ffma2(unsigned long long& d, unsigned long long a, unsigned long long b) {
    asm("fma.rn.f32x2 %0, %1, %2, %3;" : "=l"(d) : "l"(a), "l"(b), "l"(d));
}
__device__ __forceinline__ unsigned long long fadd2(unsigned long long a, unsigned long long b) {
    unsigned long long d;
    asm("add.rn.f32x2 %0, %1, %2;" : "=l"(d) : "l"(a), "l"(b));
    return d;
}
__device__ __forceinline__ unsigned long long bcast2(float x) {
    unsigned long long r;
    asm("mov.b64 %0, {%1, %1};" : "=l"(r) : "f"(x));
    return r;
}
__device__ __forceinline__ float2 unpk2(unsigned long long v) {
    float2 r;
    asm("mov.b64 {%0, %1}, %2;" : "=f"(r.x), "=f"(r.y) : "l"(v));
    return r;
}
__device__ __forceinline__ float sigf(float x) { return 1.0f / (1.0f + expf(-x)); }
__device__ __forceinline__ float geluf(float x) { return 0.5f * x * (1.0f + erff(x * 0.7071067811865475f)); }

// ---------------- prep kernels ----------------
__global__ void prep_reset() { g_fb_active = 0; }

__global__ void prep_transpose(const float* __restrict__ W_ih, const float* __restrict__ W_hh_c,
                               const float* __restrict__ W_op, const float* __restrict__ Wq,
                               const float* __restrict__ Wk,   const float* __restrict__ Wv,
                               const float* __restrict__ Wf1,  const float* __restrict__ Wf2,
                               const float* __restrict__ Wwo,  const float* __restrict__ Wr,
                               const float* __restrict__ Wfb,  const float* __restrict__ bfb)
{
    int i  = blockIdx.x * blockDim.x + threadIdx.x;
    int st = gridDim.x * blockDim.x;
    for (int p = i; p < 128 * 3072; p += st) { int k = p / 3072, o = p - k * 3072; g_WihT[p] = W_ih[o * 128 + k]; }
    for (int p = i; p < 256 * 1536; p += st) { int k = p / 1536, o = p - k * 1536; g_WhhT[p] = W_hh_c[o * 256 + k]; }
    for (int p = i; p < 256 * 512;  p += st) { int k = p >> 9,  o = p & 511;       g_WopT[p] = W_op[o * 256 + k]; }
    for (int p = i; p < 128 * 128;  p += st) {
        int k = p >> 7, d = p & 127;
        g_WqT [p] = Wq [d * 128 + k]; g_WkT [p] = Wk [d * 128 + k]; g_WvT [p] = Wv [d * 128 + k];
        g_Wf1T[p] = Wf1[d * 128 + k]; g_Wf2T[p] = Wf2[d * 128 + k]; g_WwoT[p] = Wwo[d * 128 + k];
    }
    for (int p = i; p < 512 * 100; p += st) { int k = p / 100, v = p - k * 100; g_WrT[p] = Wr[v * 512 + k]; }
    int nz = 0;
    for (int p = i; p < 128 * 128; p += st) if (Wfb[p] != 0.0f) nz = 1;
    for (int p = i; p < 128; p += st) if (bfb[p] != 0.0f) nz = 1;
    if (nz) atomicOr(&g_fb_active, 1);
}

__global__ void prep_tab(const float* __restrict__ emb, const float* __restrict__ b_ih,
                         const float* __restrict__ bfb)
{
    const int v = blockIdx.x;                 // 100 blocks
    __shared__ float se[128];
    if (threadIdx.x < 128) se[threadIdx.x] = emb[v * 128 + threadIdx.x] + bfb[threadIdx.x];
    __syncthreads();
    for (int o = threadIdx.x; o < 3072; o += blockDim.x) {
        float acc = b_ih[o];
        #pragma unroll 8
        for (int k = 0; k < 128; ++k)
            acc = fmaf(g_WihT[k * 3072 + o], se[k], acc);
        g_tab[v * 3072 + o] = acc;
    }
}

__global__ void prep_mcomb(const float* __restrict__ Wfb)
{
    if (!g_fb_active) return;
    const int k = blockIdx.x;                 // 128 blocks
    __shared__ float sw[128];
    if (threadIdx.x < 128) sw[threadIdx.x] = Wfb[k * 128 + threadIdx.x];
    __syncthreads();
    for (int o = threadIdx.x; o < 3072; o += blockDim.x) {
        float acc = 0.0f;
        #pragma unroll 8
        for (int j = 0; j < 128; ++j)
            acc = fmaf(g_WihT[j * 3072 + o], sw[j], acc);
        g_McT[k * 3072 + o] = acc;
    }
}

// ---------------- main recurrent kernel ----------------
__global__ void __launch_bounds__(512, 1)
inn_kernel(const int* __restrict__ x,
           const float* __restrict__ b_hh_c, const float* __restrict__ b_op,
           const float* __restrict__ bq, const float* __restrict__ bk, const float* __restrict__ bv,
           const float* __restrict__ bf1, const float* __restrict__ bf2, const float* __restrict__ bwo,
           const float* __restrict__ gamma, const float* __restrict__ beta,
           const float* __restrict__ br,
           float* __restrict__ out, int write_states)
{
    const int b = blockIdx.x;
    const int t = threadIdx.x;

    __shared__ __align__(16) float sh_h[4 * 256];
    __shared__ __align__(16) float sh_fb[128];
    __shared__ __align__(16) float sh_gi[3072];      // gi + generic K-split scratch
    __shared__ __align__(16) float sh_gh[1536];
    __shared__ __align__(16) float sh_o[512];
    __shared__ __align__(16) float sh_q[512];
    __shared__ __align__(16) float sh_k[512];
    __shared__ __align__(16) float sh_v[512];
    __shared__ float sh_sc[16];
    __shared__ __align__(16) float sh_mx[512];
    __shared__ __align__(16) float sh_g1[512];
    __shared__ __align__(16) float sh_pc[512];
    __shared__ __align__(16) float sh_rs[512];
    __shared__ __align__(16) float sh_on[512];
    __shared__ float sh_red[32];
    __shared__ float sh_mu[4], sh_rstd[4];

    for (int j = t; j < 1024; j += 512) sh_h[j] = 0.0f;
    if (t < 128) sh_fb[t] = 0.0f;
    const int fbact = g_fb_active;
    __syncthreads();

    const float inv_sqrt_d = 0.08838834764831845f;

    for (int s = 0; s < S_; ++s) {
        const int tok = x[b * S_ + s];

        // ---------- Stage A+B: gi = table[tok] (+ optional fb feedback matvec) ----------
        {
            const float4* trow = (const float4*)(g_tab + (size_t)tok * 3072);
            for (int u = t; u < 768; u += 512) {
                float4 v = trow[u];
                if (fbact) {
                    unsigned long long a0 = 0ull, a1 = 0ull;
                    #pragma unroll 4
                    for (int k = 0; k < 128; ++k) {
                        ulonglong2 w = *(const ulonglong2*)(g_McT + (size_t)k * 3072 + u * 4);
                        unsigned long long xx = bcast2(sh_fb[k]);
                        ffma2(a0, w.x, xx); ffma2(a1, w.y, xx);
                    }
                    float2 f0 = unpk2(a0), f1 = unpk2(a1);
                    v.x += f0.x; v.y += f0.y; v.z += f1.x; v.w += f1.y;
                }
                *(float4*)(sh_gi + u * 4) = v;
            }
        }

        // ---------- Stage C: gh (compute neurons), 384 f4-groups, K=256 ----------
        if (t < 384) {
            const int g = t;
            const float* hrow = sh_h + ((g < 192) ? 2 : 3) * 256;
            const unsigned long long* bb = (const unsigned long long*)(b_hh_c + g * 4);
            unsigned long long a0 = bb[0], a1 = bb[1];
            unsigned long long c0 = 0ull, c1 = 0ull;
            const char* wp = (const char*)(g_WhhT + g * 4);
            #pragma unroll 4
            for (int k = 0; k < 256; k += 2) {
                ulonglong2 w0 = *(const ulonglong2*)(wp + (size_t)k * 6144);
                ulonglong2 w1 = *(const ulonglong2*)(wp + (size_t)(k + 1) * 6144);
                unsigned long long x0 = bcast2(hrow[k]);
                unsigned long long x1 = bcast2(hrow[k + 1]);
                ffma2(a0, w0.x, x0); ffma2(a1, w0.y, x0);
                ffma2(c0, w1.x, x1); ffma2(c1, w1.y, x1);
            }
            a0 = fadd2(a0, c0); a1 = fadd2(a1, c1);
            float2 f0 = unpk2(a0), f1 = unpk2(a1);
            *(float4*)(sh_gh + g * 4) = make_float4(f0.x, f0.y, f1.x, f1.y);
        }
        __syncthreads();

        // ---------- Stage D: GRU gates + h update ----------
        #pragma unroll
        for (int r = 0; r < 2; ++r) {
            int j = t + r * 512;
            int n = j >> 8, hi = j & 255;
            float h_old = sh_h[n * 256 + hi];
            float gir = sh_gi[n * 768 + hi];
            float giz = sh_gi[n * 768 + 256 + hi];
            float gin = sh_gi[n * 768 + 512 + hi];
            float ghr, ghz, ghn;
            if (n < 2) { ghr = 0.0f; ghz = 5.0f; ghn = h_old; }
            else {
                int mm = n - 2;
                ghr = sh_gh[mm * 768 + hi];
                ghz = sh_gh[mm * 768 + 256 + hi];
                ghn = sh_gh[mm * 768 + 512 + hi];
            }
            float rg = sigf(gir + ghr);
            float zg = sigf(giz + ghz);
            float ng = tanhf(fmaf(rg, ghn, gin));
            sh_h[n * 256 + hi] = (1.0f - zg) * ng + zg * h_old;
        }
        __syncthreads();

        // ---------- Stage E: o = W_op @ hn + b_op ; K-split 4 x 64 ----------
        {
            const int g = t & 127, ks = t >> 7;
            const int n = g >> 5;
            const float* hrow = sh_h + n * 256 + ks * 64;
            const char* wp = (const char*)(g_WopT + (size_t)(ks * 64) * 512 + g * 4);
            unsigned long long a0 = 0ull, a1 = 0ull, c0 = 0ull, c1 = 0ull;
            #pragma unroll 4
            for (int k = 0; k < 64; k += 2) {
                ulonglong2 w0 = *(const ulonglong2*)(wp + (size_t)k * 2048);
                ulonglong2 w1 = *(const ulonglong2*)(wp + (size_t)(k + 1) * 2048);
                unsigned long long x0 = bcast2(hrow[k]);
                unsigned long long x1 = bcast2(hrow[k + 1]);
                ffma2(a0, w0.x, x0); ffma2(a1, w0.y, x0);
                ffma2(c0, w1.x, x1); ffma2(c1, w1.y, x1);
            }
            a0 = fadd2(a0, c0); a1 = fadd2(a1, c1);
            float2 f0 = unpk2(a0), f1 = unpk2(a1);
            *(float4*)(sh_gi + ks * 512 + g * 4) = make_float4(f0.x, f0.y, f1.x, f1.y);
        }
        __syncthreads();
        if (t < 128) {
            float4 a0 = *(const float4*)(sh_gi + t * 4);
            float4 a1 = *(const float4*)(sh_gi + 512 + t * 4);
            float4 a2 = *(const float4*)(sh_gi + 1024 + t * 4);
            float4 a3 = *(const float4*)(sh_gi + 1536 + t * 4);
            float4 bo = *(const float4*)(b_op + t * 4);
            *(float4*)(sh_o + t * 4) = make_float4(
                a0.x + a1.x + a2.x + a3.x + bo.x,
                a0.y + a1.y + a2.y + a3.y + bo.y,
                a0.z + a1.z + a2.z + a3.z + bo.z,
                a0.w + a1.w + a2.w + a3.w + bo.w);
        }
        __syncthreads();

        // ---------- Stage F: q,k,v ----------
        if (t < 384) {
            const int sel = t >> 7, g = t & 127;
            const int n = g >> 5, d4 = g & 31;
            const float* xrow = sh_o + n * 128;
            const float* WT = (sel == 0) ? g_WqT : (sel == 1) ? g_WkT : g_WvT;
            const float* bb = (sel == 0) ? bq : (sel == 1) ? bk : bv;
            const unsigned long long* bb2 = (const unsigned long long*)(bb + d4 * 4);
            unsigned long long a0 = bb2[0], a1 = bb2[1], c0 = 0ull, c1 = 0ull;
            const char* wp = (const char*)(WT + d4 * 4);
            #pragma unroll 4
            for (int k = 0; k < 128; k += 2) {
                ulonglong2 w0 = *(const ulonglong2*)(wp + (size_t)k * 512);
                ulonglong2 w1 = *(const ulonglong2*)(wp + (size_t)(k + 1) * 512);
                unsigned long long x0 = bcast2(xrow[k]);
                unsigned long long x1 = bcast2(xrow[k + 1]);
                ffma2(a0, w0.x, x0); ffma2(a1, w0.y, x0);
                ffma2(c0, w1.x, x1); ffma2(c1, w1.y, x1);
            }
            a0 = fadd2(a0, c0); a1 = fadd2(a1, c1);
            float2 f0 = unpk2(a0), f1 = unpk2(a1);
            float* dst = (sel == 0) ? sh_q : (sel == 1) ? sh_k : sh_v;
            *(float4*)(dst + g * 4) = make_float4(f0.x, f0.y, f1.x, f1.y);
        }
        __syncthreads();

        // ---------- Stage G: scores + softmax ----------
        {
            int w = t >> 5, l = t & 31;
            int n = w >> 2, m = w & 3;
            float sum = sh_q[n * 128 + l]      * sh_k[m * 128 + l]
                      + sh_q[n * 128 + 32 + l] * sh_k[m * 128 + 32 + l]
                      + sh_q[n * 128 + 64 + l] * sh_k[m * 128 + 64 + l]
                      + sh_q[n * 128 + 96 + l] * sh_k[m * 128 + 96 + l];
            #pragma unroll
            for (int off = 16; off; off >>= 1) sum += __shfl_down_sync(0xffffffff, sum, off);
            if (l == 0) sh_sc[n * 4 + m] = sum * inv_sqrt_d;
        }
        __syncthreads();
        if (t < 4) {
            float s0 = sh_sc[t * 4], s1 = sh_sc[t * 4 + 1], s2 = sh_sc[t * 4 + 2], s3 = sh_sc[t * 4 + 3];
            float mx = fmaxf(fmaxf(s0, s1), fmaxf(s2, s3));
            float e0 = expf(s0 - mx), e1 = expf(s1 - mx), e2 = expf(s2 - mx), e3 = expf(s3 - mx);
            float den = 1.0f / (e0 + e1 + e2 + e3);
            sh_sc[t * 4] = e0 * den; sh_sc[t * 4 + 1] = e1 * den;
            sh_sc[t * 4 + 2] = e2 * den; sh_sc[t * 4 + 3] = e3 * den;
        }
        __syncthreads();

        // ---------- Stage H: mixed ----------
        {
            int n = t >> 7, d = t & 127;
            sh_mx[t] = sh_sc[n * 4] * sh_v[d] + sh_sc[n * 4 + 1] * sh_v[128 + d]
                     + sh_sc[n * 4 + 2] * sh_v[256 + d] + sh_sc[n * 4 + 3] * sh_v[384 + d];
        }
        __syncthreads();

        // ---------- Stage I: f1 partial (K-split 4 x 32) ----------
        {
            const int g = t & 127, ks = t >> 7;
            const int n = g >> 5, d4 = g & 31;
            const float* xrow = sh_mx + n * 128 + ks * 32;
            const char* wp = (const char*)(g_Wf1T + (size_t)(ks * 32) * 128 + d4 * 4);
            unsigned long long a0 = 0ull, a1 = 0ull, c0 = 0ull, c1 = 0ull;
            #pragma unroll 4
            for (int k = 0; k < 32; k += 2) {
                ulonglong2 w0 = *(const ulonglong2*)(wp + (size_t)k * 512);
                ulonglong2 w1 = *(const ulonglong2*)(wp + (size_t)(k + 1) * 512);
                unsigned long long x0 = bcast2(xrow[k]);
                unsigned long long x1 = bcast2(xrow[k + 1]);
                ffma2(a0, w0.x, x0); ffma2(a1, w0.y, x0);
                ffma2(c0, w1.x, x1); ffma2(c1, w1.y, x1);
            }
            a0 = fadd2(a0, c0); a1 = fadd2(a1, c1);
            float2 f0 = unpk2(a0), f1 = unpk2(a1);
            *(float4*)(sh_gi + ks * 512 + g * 4) = make_float4(f0.x, f0.y, f1.x, f1.y);
        }
        __syncthreads();
        if (t < 128) {
            int d4 = t & 31;
            float4 a0 = *(const float4*)(sh_gi + t * 4);
            float4 a1 = *(const float4*)(sh_gi + 512 + t * 4);
            float4 a2 = *(const float4*)(sh_gi + 1024 + t * 4);
            float4 a3 = *(const float4*)(sh_gi + 1536 + t * 4);
            float4 bb = *(const float4*)(bf1 + d4 * 4);
            *(float4*)(sh_g1 + t * 4) = make_float4(
                geluf(a0.x + a1.x + a2.x + a3.x + bb.x),
                geluf(a0.y + a1.y + a2.y + a3.y + bb.y),
                geluf(a0.z + a1.z + a2.z + a3.z + bb.z),
                geluf(a0.w + a1.w + a2.w + a3.w + bb.w));
        }
        __syncthreads();

        // ---------- Stage J: f2 partial ----------
        {
            const int g = t & 127, ks = t >> 7;
            const int n = g >> 5, d4 = g & 31;
            const float* xrow = sh_g1 + n * 128 + ks * 32;
            const char* wp = (const char*)(g_Wf2T + (size_t)(ks * 32) * 128 + d4 * 4);
            unsigned long long a0 = 0ull, a1 = 0ull, c0 = 0ull, c1 = 0ull;
            #pragma unroll 4
            for (int k = 0; k < 32; k += 2) {
                ulonglong2 w0 = *(const ulonglong2*)(wp + (size_t)k * 512);
                ulonglong2 w1 = *(const ulonglong2*)(wp + (size_t)(k + 1) * 512);
                unsigned long long x0 = bcast2(xrow[k]);
                unsigned long long x1 = bcast2(xrow[k + 1]);
                ffma2(a0, w0.x, x0); ffma2(a1, w0.y, x0);
                ffma2(c0, w1.x, x1); ffma2(c1, w1.y, x1);
            }
            a0 = fadd2(a0, c0); a1 = fadd2(a1, c1);
            float2 f0 = unpk2(a0), f1 = unpk2(a1);
            *(float4*)(sh_gi + ks * 512 + g * 4) = make_float4(f0.x, f0.y, f1.x, f1.y);
        }
        __syncthreads();
        if (t < 128) {
            int d4 = t & 31;
            float4 a0 = *(const float4*)(sh_gi + t * 4);
            float4 a1 = *(const float4*)(sh_gi + 512 + t * 4);
            float4 a2 = *(const float4*)(sh_gi + 1024 + t * 4);
            float4 a3 = *(const float4*)(sh_gi + 1536 + t * 4);
            float4 bb = *(const float4*)(bf2 + d4 * 4);
            *(float4*)(sh_pc + t * 4) = make_float4(
                a0.x + a1.x + a2.x + a3.x + bb.x,
                a0.y + a1.y + a2.y + a3.y + bb.y,
                a0.z + a1.z + a2.z + a3.z + bb.z,
                a0.w + a1.w + a2.w + a3.w + bb.w);
        }
        __syncthreads();

        // ---------- Stage K: res = o + proc@Wwo^T + bwo ; fb = mean_n proc ----------
        {
            const int g = t & 127, ks = t >> 7;
            const int n = g >> 5, d4 = g & 31;
            const float* xrow = sh_pc + n * 128 + ks * 32;
            const char* wp = (const char*)(g_WwoT + (size_t)(ks * 32) * 128 + d4 * 4);
            unsigned long long a0 = 0ull, a1 = 0ull, c0 = 0ull, c1 = 0ull;
            #pragma unroll 4
            for (int k = 0; k < 32; k += 2) {
                ulonglong2 w0 = *(const ulonglong2*)(wp + (size_t)k * 512);
                ulonglong2 w1 = *(const ulonglong2*)(wp + (size_t)(k + 1) * 512);
                unsigned long long x0 = bcast2(xrow[k]);
                unsigned long long x1 = bcast2(xrow[k + 1]);
                ffma2(a0, w0.x, x0); ffma2(a1, w0.y, x0);
                ffma2(c0, w1.x, x1); ffma2(c1, w1.y, x1);
            }
            a0 = fadd2(a0, c0); a1 = fadd2(a1, c1);
            float2 f0 = unpk2(a0), f1 = unpk2(a1);
            *(float4*)(sh_gi + ks * 512 + g * 4) = make_float4(f0.x, f0.y, f1.x, f1.y);
        }
        __syncthreads();
        if (t < 128) {
            int d4 = t & 31;
            float4 a0 = *(const float4*)(sh_gi + t * 4);
            float4 a1 = *(const float4*)(sh_gi + 512 + t * 4);
            float4 a2 = *(const float4*)(sh_gi + 1024 + t * 4);
            float4 a3 = *(const float4*)(sh_gi + 1536 + t * 4);
            float4 bb = *(const float4*)(bwo + d4 * 4);
            float4 oo = *(const float4*)(sh_o + t * 4);
            *(float4*)(sh_rs + t * 4) = make_float4(
                oo.x + a0.x + a1.x + a2.x + a3.x + bb.x,
                oo.y + a0.y + a1.y + a2.y + a3.y + bb.y,
                oo.z + a0.z + a1.z + a2.z + a3.z + bb.z,
                oo.w + a0.w + a1.w + a2.w + a3.w + bb.w);
            sh_fb[t] = 0.25f * (sh_pc[t] + sh_pc[128 + t] + sh_pc[256 + t] + sh_pc[384 + t]);
        }
        __syncthreads();

        // ---------- Stage L: LayerNorm ----------
        {
            float v = sh_rs[t];
            float sum = v, sq = v * v;
            #pragma unroll
            for (int off = 16; off; off >>= 1) {
                sum += __shfl_down_sync(0xffffffff, sum, off);
                sq  += __shfl_down_sync(0xffffffff, sq,  off);
            }
            if ((t & 31) == 0) { sh_red[(t >> 5) * 2] = sum; sh_red[(t >> 5) * 2 + 1] = sq; }
        }
        __syncthreads();
        if (t < 4) {
            float sum = 0.f, sq = 0.f;
            #pragma unroll
            for (int w = t * 4; w < t * 4 + 4; ++w) { sum += sh_red[w * 2]; sq += sh_red[w * 2 + 1]; }
            float mu = sum * (1.0f / 128.0f);
            float var = sq * (1.0f / 128.0f) - mu * mu;
            sh_mu[t] = mu;
            sh_rstd[t] = rsqrtf(var + 1e-5f);
        }
        __syncthreads();
        {
            int n = t >> 7, d = t & 127;
            sh_on[t] = (sh_rs[t] - sh_mu[n]) * sh_rstd[n] * gamma[d] + beta[d];
        }
        __syncthreads();

        // ---------- Stage M: logits ----------
        {
            int g2 = t >> 7, v = t & 127;
            float acc = 0.0f;
            if (v < 100) {
                #pragma unroll 8
                for (int k = g2 * 128; k < g2 * 128 + 128; ++k)
                    acc = fmaf(g_WrT[k * 100 + v], sh_on[k], acc);
            }
            sh_gi[g2 * 128 + v] = acc;
        }
        __syncthreads();
        if (t < 100)
            out[(size_t)b * S_ * V_ + (size_t)s * V_ + t] =
                sh_gi[t] + sh_gi[128 + t] + sh_gi[256 + t] + sh_gi[384 + t] + br[t];
        __syncthreads();
    }

    if (write_states) {
        size_t OFF1 = (size_t)B_ * S_ * V_;
        for (int j = t; j < 1024; j += 512) {
            int n = j >> 8, k = j & 255;
            out[OFF1 + (size_t)n * B_ * H_ + (size_t)b * H_ + k] = sh_h[j];
        }
        if (t < 128)
            out[OFF1 + (size_t)N_ * B_ * H_ + (size_t)b * D_ + t] = sh_fb[t];
    }
}

extern "C" void kernel_launch(void* const* d_in, const int* in_sizes, int n_in,
                              void* d_out, int out_size)
{
    const int*   x      = (const int*)  d_in[0];
    const float* emb    = (const float*)d_in[1];
    const float* W_ih   = (const float*)d_in[2];
    const float* b_ih   = (const float*)d_in[3];
    const float* W_hh_c = (const float*)d_in[4];
    const float* b_hh_c = (const float*)d_in[5];
    const float* W_op   = (const float*)d_in[6];
    const float* b_op   = (const float*)d_in[7];
    const float* Wq     = (const float*)d_in[8];
    const float* bq     = (const float*)d_in[9];
    const float* Wk     = (const float*)d_in[10];
    const float* bk     = (const float*)d_in[11];
    const float* Wv     = (const float*)d_in[12];
    const float* bv     = (const float*)d_in[13];
    const float* Wf1    = (const float*)d_in[14];
    const float* bf1    = (const float*)d_in[15];
    const float* Wf2    = (const float*)d_in[16];
    const float* bf2    = (const float*)d_in[17];
    const float* Wwo    = (const float*)d_in[18];
    const float* bwo    = (const float*)d_in[19];
    const float* gamma  = (const float*)d_in[20];
    const float* beta   = (const float*)d_in[21];
    const float* Wr     = (const float*)d_in[22];
    const float* br     = (const float*)d_in[23];
    const float* Wfb    = (const float*)d_in[24];
    const float* bfb    = (const float*)d_in[25];
    float* out = (float*)d_out;

    prep_reset<<<1, 1>>>();
    prep_transpose<<<512, 256>>>(W_ih, W_hh_c, W_op, Wq, Wk, Wv, Wf1, Wf2, Wwo, Wr, Wfb, bfb);
    prep_tab<<<100, 256>>>(emb, b_ih, bfb);
    prep_mcomb<<<128, 256>>>(Wfb);

    long long FULL = (long long)B_ * S_ * V_ + (long long)N_ * B_ * H_ + (long long)B_ * D_;
    int write_states = ((long long)out_size >= FULL) ? 1 : 0;

    inn_kernel<<<B_, 512>>>(x, b_hh_c, b_op, bq, bk, bv, bf1, bf2, bwo,
                            gamma, beta, br, out, write_states);
}

// round 3
// speedup vs baseline: 2.1017x; 1.0023x over previous
#include <cuda_runtime.h>
#include <math.h>

#define D_ 128
#define H_ 256
#define N_ 4
#define V_ 100
#define B_ 64
#define S_ 2048

// ---- Device-global weights (transposed, column-major [k][out]) ----
__device__ __align__(16) float g_WihT[128 * 3072];   // for prep only
__device__ __align__(16) float g_WhhT[256 * 1536];
__device__ __align__(16) float g_WopT[256 * 512];
__device__ __align__(16) float g_WqT [128 * 128];
__device__ __align__(16) float g_WkT [128 * 128];
__device__ __align__(16) float g_WvT [128 * 128];
__device__ __align__(16) float g_Wf1T[128 * 128];
__device__ __align__(16) float g_Wf2T[128 * 128];
__device__ __align__(16) float g_WwoT[128 * 128];
__device__ __align__(16) float g_WrT [512 * 100];
__device__ __align__(16) float g_tab [100 * 3072];   // gi table: W_ih@(emb[v]+bfb) + b_ih
__device__ __align__(16) float g_McT [128 * 3072];   // (W_ih@Wfb^T) transposed, fallback only
__device__ int g_fb_active;

// ---------------- f32x2 packed helpers ----------------
__device__ __forceinline__ void ffma2(unsigned long long& d, unsigned long long a, unsigned long long b) {
    asm("fma.rn.f32x2 %0, %1, %2, %3;" : "=l"(d) : "l"(a), "l"(b), "l"(d));
}
__device__ __forceinline__ unsigned long long fadd2(unsigned long long a, unsigned long long b) {
    unsigned long long d;
    asm("add.rn.f32x2 %0, %1, %2;" : "=l"(d) : "l"(a), "l"(b));
    return d;
}
__device__ __forceinline__ unsigned long long bcast2(float x) {
    unsigned long long r;
    asm("mov.b64 %0, {%1, %1};" : "=l"(r) : "f"(x));
    return r;
}
__device__ __forceinline__ float2 unpk2(unsigned long long v) {
    float2 r;
    asm("mov.b64 {%0, %1}, %2;" : "=f"(r.x), "=f"(r.y) : "l"(v));
    return r;
}
__device__ __forceinline__ float sigf(float x) { return 1.0f / (1.0f + expf(-x)); }
__device__ __forceinline__ float geluf(float x) { return 0.5f * x * (1.0f + erff(x * 0.7071067811865475f)); }

// ---------------- prep kernels ----------------
__global__ void prep_reset() { g_fb_active = 0; }

__global__ void prep_transpose(const float* __restrict__ W_ih, const float* __restrict__ W_hh_c,
                               const float* __restrict__ W_op, const float* __restrict__ Wq,
                               const float* __restrict__ Wk,   const float* __restrict__ Wv,
                               const float* __restrict__ Wf1,  const float* __restrict__ Wf2,
                               const float* __restrict__ Wwo,  const float* __restrict__ Wr,
                               const float* __restrict__ Wfb,  const float* __restrict__ bfb)
{
    int i  = blockIdx.x * blockDim.x + threadIdx.x;
    int st = gridDim.x * blockDim.x;
    for (int p = i; p < 128 * 3072; p += st) { int k = p / 3072, o = p - k * 3072; g_WihT[p] = W_ih[o * 128 + k]; }
    for (int p = i; p < 256 * 1536; p += st) { int k = p / 1536, o = p - k * 1536; g_WhhT[p] = W_hh_c[o * 256 + k]; }
    for (int p = i; p < 256 * 512;  p += st) { int k = p >> 9,  o = p & 511;       g_WopT[p] = W_op[o * 256 + k]; }
    for (int p = i; p < 128 * 128;  p += st) {
        int k = p >> 7, d = p & 127;
        g_WqT [p] = Wq [d * 128 + k]; g_WkT [p] = Wk [d * 128 + k]; g_WvT [p] = Wv [d * 128 + k];
        g_Wf1T[p] = Wf1[d * 128 + k]; g_Wf2T[p] = Wf2[d * 128 + k]; g_WwoT[p] = Wwo[d * 128 + k];
    }
    for (int p = i; p < 512 * 100; p += st) { int k = p / 100, v = p - k * 100; g_WrT[p] = Wr[v * 512 + k]; }
    int nz = 0;
    for (int p = i; p < 128 * 128; p += st) if (Wfb[p] != 0.0f) nz = 1;
    for (int p = i; p < 128; p += st) if (bfb[p] != 0.0f) nz = 1;
    if (nz) atomicOr(&g_fb_active, 1);
}

__global__ void prep_tab(const float* __restrict__ emb, const float* __restrict__ b_ih,
                         const float* __restrict__ bfb)
{
    const int v = blockIdx.x;                 // 100 blocks
    __shared__ float se[128];
    if (threadIdx.x < 128) se[threadIdx.x] = emb[v * 128 + threadIdx.x] + bfb[threadIdx.x];
    __syncthreads();
    for (int o = threadIdx.x; o < 3072; o += blockDim.x) {
        float acc = b_ih[o];
        #pragma unroll 8
        for (int k = 0; k < 128; ++k)
            acc = fmaf(g_WihT[k * 3072 + o], se[k], acc);
        g_tab[v * 3072 + o] = acc;
    }
}

__global__ void prep_mcomb(const float* __restrict__ Wfb)
{
    if (!g_fb_active) return;
    const int k = blockIdx.x;                 // 128 blocks
    __shared__ float sw[128];
    if (threadIdx.x < 128) sw[threadIdx.x] = Wfb[k * 128 + threadIdx.x];
    __syncthreads();
    for (int o = threadIdx.x; o < 3072; o += blockDim.x) {
        float acc = 0.0f;
        #pragma unroll 8
        for (int j = 0; j < 128; ++j)
            acc = fmaf(g_WihT[j * 3072 + o], sw[j], acc);
        g_McT[k * 3072 + o] = acc;
    }
}

// ---------------- main recurrent kernel ----------------
__global__ void __launch_bounds__(512, 1)
inn_kernel(const int* __restrict__ x,
           const float* __restrict__ b_hh_c, const float* __restrict__ b_op,
           const float* __restrict__ bq, const float* __restrict__ bk, const float* __restrict__ bv,
           const float* __restrict__ bf1, const float* __restrict__ bf2, const float* __restrict__ bwo,
           const float* __restrict__ gamma, const float* __restrict__ beta,
           const float* __restrict__ br,
           float* __restrict__ out, int write_states)
{
    const int b = blockIdx.x;
    const int t = threadIdx.x;

    __shared__ __align__(16) float sh_h[4 * 256];
    __shared__ __align__(16) float sh_fb[128];
    __shared__ __align__(16) float sh_gi[3072];      // gi + generic K-split scratch
    __shared__ __align__(16) float sh_gh[1536];
    __shared__ __align__(16) float sh_o[512];
    __shared__ __align__(16) float sh_q[512];
    __shared__ __align__(16) float sh_k[512];
    __shared__ __align__(16) float sh_v[512];
    __shared__ float sh_sc[16];
    __shared__ __align__(16) float sh_mx[512];
    __shared__ __align__(16) float sh_g1[512];
    __shared__ __align__(16) float sh_pc[512];
    __shared__ __align__(16) float sh_rs[512];
    __shared__ __align__(16) float sh_on[512];
    __shared__ float sh_red[32];
    __shared__ float sh_mu[4], sh_rstd[4];

    for (int j = t; j < 1024; j += 512) sh_h[j] = 0.0f;
    if (t < 128) sh_fb[t] = 0.0f;
    const int fbact = g_fb_active;
    __syncthreads();

    const float inv_sqrt_d = 0.08838834764831845f;

    for (int s = 0; s < S_; ++s) {
        const int tok = x[b * S_ + s];

        // ---------- Stage A+B: gi = table[tok] (+ optional fb feedback matvec) ----------
        {
            const float4* trow = (const float4*)(g_tab + (size_t)tok * 3072);
            for (int u = t; u < 768; u += 512) {
                float4 v = trow[u];
                if (fbact) {
                    unsigned long long a0 = 0ull, a1 = 0ull;
                    #pragma unroll 4
                    for (int k = 0; k < 128; ++k) {
                        ulonglong2 w = *(const ulonglong2*)(g_McT + (size_t)k * 3072 + u * 4);
                        unsigned long long xx = bcast2(sh_fb[k]);
                        ffma2(a0, w.x, xx); ffma2(a1, w.y, xx);
                    }
                    float2 f0 = unpk2(a0), f1 = unpk2(a1);
                    v.x += f0.x; v.y += f0.y; v.z += f1.x; v.w += f1.y;
                }
                *(float4*)(sh_gi + u * 4) = v;
            }
        }

        // ---------- Stage C: gh (compute neurons), 384 f4-groups, K=256 ----------
        if (t < 384) {
            const int g = t;
            const float* hrow = sh_h + ((g < 192) ? 2 : 3) * 256;
            const unsigned long long* bb = (const unsigned long long*)(b_hh_c + g * 4);
            unsigned long long a0 = bb[0], a1 = bb[1];
            unsigned long long c0 = 0ull, c1 = 0ull;
            const char* wp = (const char*)(g_WhhT + g * 4);
            #pragma unroll 4
            for (int k = 0; k < 256; k += 2) {
                ulonglong2 w0 = *(const ulonglong2*)(wp + (size_t)k * 6144);
                ulonglong2 w1 = *(const ulonglong2*)(wp + (size_t)(k + 1) * 6144);
                unsigned long long x0 = bcast2(hrow[k]);
                unsigned long long x1 = bcast2(hrow[k + 1]);
                ffma2(a0, w0.x, x0); ffma2(a1, w0.y, x0);
                ffma2(c0, w1.x, x1); ffma2(c1, w1.y, x1);
            }
            a0 = fadd2(a0, c0); a1 = fadd2(a1, c1);
            float2 f0 = unpk2(a0), f1 = unpk2(a1);
            *(float4*)(sh_gh + g * 4) = make_float4(f0.x, f0.y, f1.x, f1.y);
        }
        __syncthreads();

        // ---------- Stage D: GRU gates + h update ----------
        #pragma unroll
        for (int r = 0; r < 2; ++r) {
            int j = t + r * 512;
            int n = j >> 8, hi = j & 255;
            float h_old = sh_h[n * 256 + hi];
            float gir = sh_gi[n * 768 + hi];
            float giz = sh_gi[n * 768 + 256 + hi];
            float gin = sh_gi[n * 768 + 512 + hi];
            float ghr, ghz, ghn;
            if (n < 2) { ghr = 0.0f; ghz = 5.0f; ghn = h_old; }
            else {
                int mm = n - 2;
                ghr = sh_gh[mm * 768 + hi];
                ghz = sh_gh[mm * 768 + 256 + hi];
                ghn = sh_gh[mm * 768 + 512 + hi];
            }
            float rg = sigf(gir + ghr);
            float zg = sigf(giz + ghz);
            float ng = tanhf(fmaf(rg, ghn, gin));
            sh_h[n * 256 + hi] = (1.0f - zg) * ng + zg * h_old;
        }
        __syncthreads();

        // ---------- Stage E: o = W_op @ hn + b_op ; K-split 4 x 64 ----------
        {
            const int g = t & 127, ks = t >> 7;
            const int n = g >> 5;
            const float* hrow = sh_h + n * 256 + ks * 64;
            const char* wp = (const char*)(g_WopT + (size_t)(ks * 64) * 512 + g * 4);
            unsigned long long a0 = 0ull, a1 = 0ull, c0 = 0ull, c1 = 0ull;
            #pragma unroll 4
            for (int k = 0; k < 64; k += 2) {
                ulonglong2 w0 = *(const ulonglong2*)(wp + (size_t)k * 2048);
                ulonglong2 w1 = *(const ulonglong2*)(wp + (size_t)(k + 1) * 2048);
                unsigned long long x0 = bcast2(hrow[k]);
                unsigned long long x1 = bcast2(hrow[k + 1]);
                ffma2(a0, w0.x, x0); ffma2(a1, w0.y, x0);
                ffma2(c0, w1.x, x1); ffma2(c1, w1.y, x1);
            }
            a0 = fadd2(a0, c0); a1 = fadd2(a1, c1);
            float2 f0 = unpk2(a0), f1 = unpk2(a1);
            *(float4*)(sh_gi + ks * 512 + g * 4) = make_float4(f0.x, f0.y, f1.x, f1.y);
        }
        __syncthreads();
        if (t < 128) {
            float4 a0 = *(const float4*)(sh_gi + t * 4);
            float4 a1 = *(const float4*)(sh_gi + 512 + t * 4);
            float4 a2 = *(const float4*)(sh_gi + 1024 + t * 4);
            float4 a3 = *(const float4*)(sh_gi + 1536 + t * 4);
            float4 bo = *(const float4*)(b_op + t * 4);
            *(float4*)(sh_o + t * 4) = make_float4(
                a0.x + a1.x + a2.x + a3.x + bo.x,
                a0.y + a1.y + a2.y + a3.y + bo.y,
                a0.z + a1.z + a2.z + a3.z + bo.z,
                a0.w + a1.w + a2.w + a3.w + bo.w);
        }
        __syncthreads();

        // ---------- Stage F: q,k,v ----------
        if (t < 384) {
            const int sel = t >> 7, g = t & 127;
            const int n = g >> 5, d4 = g & 31;
            const float* xrow = sh_o + n * 128;
            const float* WT = (sel == 0) ? g_WqT : (sel == 1) ? g_WkT : g_WvT;
            const float* bb = (sel == 0) ? bq : (sel == 1) ? bk : bv;
            const unsigned long long* bb2 = (const unsigned long long*)(bb + d4 * 4);
            unsigned long long a0 = bb2[0], a1 = bb2[1], c0 = 0ull, c1 = 0ull;
            const char* wp = (const char*)(WT + d4 * 4);
            #pragma unroll 4
            for (int k = 0; k < 128; k += 2) {
                ulonglong2 w0 = *(const ulonglong2*)(wp + (size_t)k * 512);
                ulonglong2 w1 = *(const ulonglong2*)(wp + (size_t)(k + 1) * 512);
                unsigned long long x0 = bcast2(xrow[k]);
                unsigned long long x1 = bcast2(xrow[k + 1]);
                ffma2(a0, w0.x, x0); ffma2(a1, w0.y, x0);
                ffma2(c0, w1.x, x1); ffma2(c1, w1.y, x1);
            }
            a0 = fadd2(a0, c0); a1 = fadd2(a1, c1);
            float2 f0 = unpk2(a0), f1 = unpk2(a1);
            float* dst = (sel == 0) ? sh_q : (sel == 1) ? sh_k : sh_v;
            *(float4*)(dst + g * 4) = make_float4(f0.x, f0.y, f1.x, f1.y);
        }
        __syncthreads();

        // ---------- Stage G: scores + softmax ----------
        {
            int w = t >> 5, l = t & 31;
            int n = w >> 2, m = w & 3;
            float sum = sh_q[n * 128 + l]      * sh_k[m * 128 + l]
                      + sh_q[n * 128 + 32 + l] * sh_k[m * 128 + 32 + l]
                      + sh_q[n * 128 + 64 + l] * sh_k[m * 128 + 64 + l]
                      + sh_q[n * 128 + 96 + l] * sh_k[m * 128 + 96 + l];
            #pragma unroll
            for (int off = 16; off; off >>= 1) sum += __shfl_down_sync(0xffffffff, sum, off);
            if (l == 0) sh_sc[n * 4 + m] = sum * inv_sqrt_d;
        }
        __syncthreads();
        if (t < 4) {
            float s0 = sh_sc[t * 4], s1 = sh_sc[t * 4 + 1], s2 = sh_sc[t * 4 + 2], s3 = sh_sc[t * 4 + 3];
            float mx = fmaxf(fmaxf(s0, s1), fmaxf(s2, s3));
            float e0 = expf(s0 - mx), e1 = expf(s1 - mx), e2 = expf(s2 - mx), e3 = expf(s3 - mx);
            float den = 1.0f / (e0 + e1 + e2 + e3);
            sh_sc[t * 4] = e0 * den; sh_sc[t * 4 + 1] = e1 * den;
            sh_sc[t * 4 + 2] = e2 * den; sh_sc[t * 4 + 3] = e3 * den;
        }
        __syncthreads();

        // ---------- Stage H: mixed ----------
        {
            int n = t >> 7, d = t & 127;
            sh_mx[t] = sh_sc[n * 4] * sh_v[d] + sh_sc[n * 4 + 1] * sh_v[128 + d]
                     + sh_sc[n * 4 + 2] * sh_v[256 + d] + sh_sc[n * 4 + 3] * sh_v[384 + d];
        }
        __syncthreads();

        // ---------- Stage I: f1 partial (K-split 4 x 32) ----------
        {
            const int g = t & 127, ks = t >> 7;
            const int n = g >> 5, d4 = g & 31;
            const float* xrow = sh_mx + n * 128 + ks * 32;
            const char* wp = (const char*)(g_Wf1T + (size_t)(ks * 32) * 128 + d4 * 4);
            unsigned long long a0 = 0ull, a1 = 0ull, c0 = 0ull, c1 = 0ull;
            #pragma unroll 4
            for (int k = 0; k < 32; k += 2) {
                ulonglong2 w0 = *(const ulonglong2*)(wp + (size_t)k * 512);
                ulonglong2 w1 = *(const ulonglong2*)(wp + (size_t)(k + 1) * 512);
                unsigned long long x0 = bcast2(xrow[k]);
                unsigned long long x1 = bcast2(xrow[k + 1]);
                ffma2(a0, w0.x, x0); ffma2(a1, w0.y, x0);
                ffma2(c0, w1.x, x1); ffma2(c1, w1.y, x1);
            }
            a0 = fadd2(a0, c0); a1 = fadd2(a1, c1);
            float2 f0 = unpk2(a0), f1 = unpk2(a1);
            *(float4*)(sh_gi + ks * 512 + g * 4) = make_float4(f0.x, f0.y, f1.x, f1.y);
        }
        __syncthreads();
        if (t < 128) {
            int d4 = t & 31;
            float4 a0 = *(const float4*)(sh_gi + t * 4);
            float4 a1 = *(const float4*)(sh_gi + 512 + t * 4);
            float4 a2 = *(const float4*)(sh_gi + 1024 + t * 4);
            float4 a3 = *(const float4*)(sh_gi + 1536 + t * 4);
            float4 bb = *(const float4*)(bf1 + d4 * 4);
            *(float4*)(sh_g1 + t * 4) = make_float4(
                geluf(a0.x + a1.x + a2.x + a3.x + bb.x),
                geluf(a0.y + a1.y + a2.y + a3.y + bb.y),
                geluf(a0.z + a1.z + a2.z + a3.z + bb.z),
                geluf(a0.w + a1.w + a2.w + a3.w + bb.w));
        }
        __syncthreads();

        // ---------- Stage J: f2 partial ----------
        {
            const int g = t & 127, ks = t >> 7;
            const int n = g >> 5, d4 = g & 31;
            const float* xrow = sh_g1 + n * 128 + ks * 32;
            const char* wp = (const char*)(g_Wf2T + (size_t)(ks * 32) * 128 + d4 * 4);
            unsigned long long a0 = 0ull, a1 = 0ull, c0 = 0ull, c1 = 0ull;
            #pragma unroll 4
            for (int k = 0; k < 32; k += 2) {
                ulonglong2 w0 = *(const ulonglong2*)(wp + (size_t)k * 512);
                ulonglong2 w1 = *(const ulonglong2*)(wp + (size_t)(k + 1) * 512);
                unsigned long long x0 = bcast2(xrow[k]);
                unsigned long long x1 = bcast2(xrow[k + 1]);
                ffma2(a0, w0.x, x0); ffma2(a1, w0.y, x0);
                ffma2(c0, w1.x, x1); ffma2(c1, w1.y, x1);
            }
            a0 = fadd2(a0, c0); a1 = fadd2(a1, c1);
            float2 f0 = unpk2(a0), f1 = unpk2(a1);
            *(float4*)(sh_gi + ks * 512 + g * 4) = make_float4(f0.x, f0.y, f1.x, f1.y);
        }
        __syncthreads();
        if (t < 128) {
            int d4 = t & 31;
            float4 a0 = *(const float4*)(sh_gi + t * 4);
            float4 a1 = *(const float4*)(sh_gi + 512 + t * 4);
            float4 a2 = *(const float4*)(sh_gi + 1024 + t * 4);
            float4 a3 = *(const float4*)(sh_gi + 1536 + t * 4);
            float4 bb = *(const float4*)(bf2 + d4 * 4);
            *(float4*)(sh_pc + t * 4) = make_float4(
                a0.x + a1.x + a2.x + a3.x + bb.x,
                a0.y + a1.y + a2.y + a3.y + bb.y,
                a0.z + a1.z + a2.z + a3.z + bb.z,
                a0.w + a1.w + a2.w + a3.w + bb.w);
        }
        __syncthreads();

        // ---------- Stage K: res = o + proc@Wwo^T + bwo ; fb = mean_n proc ----------
        {
            const int g = t & 127, ks = t >> 7;
            const int n = g >> 5, d4 = g & 31;
            const float* xrow = sh_pc + n * 128 + ks * 32;
            const char* wp = (const char*)(g_WwoT + (size_t)(ks * 32) * 128 + d4 * 4);
            unsigned long long a0 = 0ull, a1 = 0ull, c0 = 0ull, c1 = 0ull;
            #pragma unroll 4
            for (int k = 0; k < 32; k += 2) {
                ulonglong2 w0 = *(const ulonglong2*)(wp + (size_t)k * 512);
                ulonglong2 w1 = *(const ulonglong2*)(wp + (size_t)(k + 1) * 512);
                unsigned long long x0 = bcast2(xrow[k]);
                unsigned long long x1 = bcast2(xrow[k + 1]);
                ffma2(a0, w0.x, x0); ffma2(a1, w0.y, x0);
                ffma2(c0, w1.x, x1); ffma2(c1, w1.y, x1);
            }
            a0 = fadd2(a0, c0); a1 = fadd2(a1, c1);
            float2 f0 = unpk2(a0), f1 = unpk2(a1);
            *(float4*)(sh_gi + ks * 512 + g * 4) = make_float4(f0.x, f0.y, f1.x, f1.y);
        }
        __syncthreads();
        if (t < 128) {
            int d4 = t & 31;
            float4 a0 = *(const float4*)(sh_gi + t * 4);
            float4 a1 = *(const float4*)(sh_gi + 512 + t * 4);
            float4 a2 = *(const float4*)(sh_gi + 1024 + t * 4);
            float4 a3 = *(const float4*)(sh_gi + 1536 + t * 4);
            float4 bb = *(const float4*)(bwo + d4 * 4);
            float4 oo = *(const float4*)(sh_o + t * 4);
            *(float4*)(sh_rs + t * 4) = make_float4(
                oo.x + a0.x + a1.x + a2.x + a3.x + bb.x,
                oo.y + a0.y + a1.y + a2.y + a3.y + bb.y,
                oo.z + a0.z + a1.z + a2.z + a3.z + bb.z,
                oo.w + a0.w + a1.w + a2.w + a3.w + bb.w);
            sh_fb[t] = 0.25f * (sh_pc[t] + sh_pc[128 + t] + sh_pc[256 + t] + sh_pc[384 + t]);
        }
        __syncthreads();

        // ---------- Stage L: LayerNorm ----------
        {
            float v = sh_rs[t];
            float sum = v, sq = v * v;
            #pragma unroll
            for (int off = 16; off; off >>= 1) {
                sum += __shfl_down_sync(0xffffffff, sum, off);
                sq  += __shfl_down_sync(0xffffffff, sq,  off);
            }
            if ((t & 31) == 0) { sh_red[(t >> 5) * 2] = sum; sh_red[(t >> 5) * 2 + 1] = sq; }
        }
        __syncthreads();
        if (t < 4) {
            float sum = 0.f, sq = 0.f;
            #pragma unroll
            for (int w = t * 4; w < t * 4 + 4; ++w) { sum += sh_red[w * 2]; sq += sh_red[w * 2 + 1]; }
            float mu = sum * (1.0f / 128.0f);
            float var = sq * (1.0f / 128.0f) - mu * mu;
            sh_mu[t] = mu;
            sh_rstd[t] = rsqrtf(var + 1e-5f);
        }
        __syncthreads();
        {
            int n = t >> 7, d = t & 127;
            sh_on[t] = (sh_rs[t] - sh_mu[n]) * sh_rstd[n] * gamma[d] + beta[d];
        }
        __syncthreads();

        // ---------- Stage M: logits ----------
        {
            int g2 = t >> 7, v = t & 127;
            float acc = 0.0f;
            if (v < 100) {
                #pragma unroll 8
                for (int k = g2 * 128; k < g2 * 128 + 128; ++k)
                    acc = fmaf(g_WrT[k * 100 + v], sh_on[k], acc);
            }
            sh_gi[g2 * 128 + v] = acc;
        }
        __syncthreads();
        if (t < 100)
            out[(size_t)b * S_ * V_ + (size_t)s * V_ + t] =
                sh_gi[t] + sh_gi[128 + t] + sh_gi[256 + t] + sh_gi[384 + t] + br[t];
        __syncthreads();
    }

    if (write_states) {
        size_t OFF1 = (size_t)B_ * S_ * V_;
        for (int j = t; j < 1024; j += 512) {
            int n = j >> 8, k = j & 255;
            out[OFF1 + (size_t)n * B_ * H_ + (size_t)b * H_ + k] = sh_h[j];
        }
        if (t < 128)
            out[OFF1 + (size_t)N_ * B_ * H_ + (size_t)b * D_ + t] = sh_fb[t];
    }
}

extern "C" void kernel_launch(void* const* d_in, const int* in_sizes, int n_in,
                              void* d_out, int out_size)
{
    const int*   x      = (const int*)  d_in[0];
    const float* emb    = (const float*)d_in[1];
    const float* W_ih   = (const float*)d_in[2];
    const float* b_ih   = (const float*)d_in[3];
    const float* W_hh_c = (const float*)d_in[4];
    const float* b_hh_c = (const float*)d_in[5];
    const float* W_op   = (const float*)d_in[6];
    const float* b_op   = (const float*)d_in[7];
    const float* Wq     = (const float*)d_in[8];
    const float* bq     = (const float*)d_in[9];
    const float* Wk     = (const float*)d_in[10];
    const float* bk     = (const float*)d_in[11];
    const float* Wv     = (const float*)d_in[12];
    const float* bv     = (const float*)d_in[13];
    const float* Wf1    = (const float*)d_in[14];
    const float* bf1    = (const float*)d_in[15];
    const float* Wf2    = (const float*)d_in[16];
    const float* bf2    = (const float*)d_in[17];
    const float* Wwo    = (const float*)d_in[18];
    const float* bwo    = (const float*)d_in[19];
    const float* gamma  = (const float*)d_in[20];
    const float* beta   = (const float*)d_in[21];
    const float* Wr     = (const float*)d_in[22];
    const float* br     = (const float*)d_in[23];
    const float* Wfb    = (const float*)d_in[24];
    const float* bfb    = (const float*)d_in[25];
    float* out = (float*)d_out;

    prep_reset<<<1, 1>>>();
    prep_transpose<<<512, 256>>>(W_ih, W_hh_c, W_op, Wq, Wk, Wv, Wf1, Wf2, Wwo, Wr, Wfb, bfb);
    prep_tab<<<100, 256>>>(emb, b_ih, bfb);
    prep_mcomb<<<128, 256>>>(Wfb);

    long long FULL = (long long)B_ * S_ * V_ + (long long)N_ * B_ * H_ + (long long)B_ * D_;
    int write_states = ((long long)out_size >= FULL) ? 1 : 0;

    inn_kernel<<<B_, 512>>>(x, b_hh_c, b_op, bq, bk, bv, bf1, bf2, bwo,
                            gamma, beta, br, out, write_states);
}

// round 4
// speedup vs baseline: 2.6626x; 1.2669x over previous
#include <cuda_runtime.h>
#include <math.h>

#define S_ 2048
#define V_ 100
#define B_ 64
#define H_ 256
#define N_ 4
#define D_ 128

__device__ __align__(16) float g_WihT[128 * 3072];
__device__ __align__(16) float g_WhhT[256 * 1536];
__device__ __align__(16) float g_WopT[256 * 512];
__device__ __align__(16) float g_WqT [16384], g_WkT [16384], g_WvT [16384];
__device__ __align__(16) float g_Wf1T[16384], g_Wf2T[16384], g_WwoT[16384];
__device__ __align__(16) float g_WrT [512 * 100];
__device__ __align__(16) float g_tab [100 * 3072];
__device__ __align__(16) float g_McT [128 * 3072];
__device__ int g_fb_active;

__device__ __forceinline__ void ffma2(unsigned long long& d, unsigned long long a, unsigned long long b) {
    asm("fma.rn.f32x2 %0, %1, %2, %3;" : "=l"(d) : "l"(a), "l"(b), "l"(d));
}
__device__ __forceinline__ unsigned long long bcast2(float x) {
    unsigned long long r; asm("mov.b64 %0, {%1, %1};" : "=l"(r) : "f"(x)); return r;
}
__device__ __forceinline__ float sigf(float x) { return 1.0f / (1.0f + expf(-x)); }
__device__ __forceinline__ float geluf(float x) { return 0.5f * x * (1.0f + erff(x * 0.7071067811865475f)); }

// ---------------- prep ----------------
__global__ void prep_reset() { g_fb_active = 0; }

__global__ void prep_transpose(const float* __restrict__ W_ih, const float* __restrict__ W_hh_c,
                               const float* __restrict__ W_op, const float* __restrict__ Wq,
                               const float* __restrict__ Wk,   const float* __restrict__ Wv,
                               const float* __restrict__ Wf1,  const float* __restrict__ Wf2,
                               const float* __restrict__ Wwo,  const float* __restrict__ Wr,
                               const float* __restrict__ Wfb,  const float* __restrict__ bfb)
{
    int i = blockIdx.x * blockDim.x + threadIdx.x, st = gridDim.x * blockDim.x;
    for (int p = i; p < 128 * 3072; p += st) { int k = p / 3072, o = p - k * 3072; g_WihT[p] = W_ih[o * 128 + k]; }
    for (int p = i; p < 256 * 1536; p += st) { int k = p / 1536, o = p - k * 1536; g_WhhT[p] = W_hh_c[o * 256 + k]; }
    for (int p = i; p < 256 * 512;  p += st) { int k = p >> 9,  o = p & 511;       g_WopT[p] = W_op[o * 256 + k]; }
    for (int p = i; p < 16384; p += st) {
        int k = p >> 7, d = p & 127;
        g_WqT [p] = Wq [d * 128 + k]; g_WkT [p] = Wk [d * 128 + k]; g_WvT [p] = Wv [d * 128 + k];
        g_Wf1T[p] = Wf1[d * 128 + k]; g_Wf2T[p] = Wf2[d * 128 + k]; g_WwoT[p] = Wwo[d * 128 + k];
    }
    for (int p = i; p < 512 * 100; p += st) { int k = p / 100, v = p - k * 100; g_WrT[p] = Wr[v * 512 + k]; }
    int nz = 0;
    for (int p = i; p < 16384; p += st) if (Wfb[p] != 0.0f) nz = 1;
    for (int p = i; p < 128; p += st) if (bfb[p] != 0.0f) nz = 1;
    if (nz) atomicOr(&g_fb_active, 1);
}

__global__ void prep_tab(const float* __restrict__ emb, const float* __restrict__ b_ih,
                         const float* __restrict__ bfb)
{
    const int v = blockIdx.x;
    __shared__ float se[128];
    if (threadIdx.x < 128) se[threadIdx.x] = emb[v * 128 + threadIdx.x] + bfb[threadIdx.x];
    __syncthreads();
    for (int o = threadIdx.x; o < 3072; o += blockDim.x) {
        float acc = b_ih[o];
        #pragma unroll 8
        for (int k = 0; k < 128; ++k) acc = fmaf(g_WihT[k * 3072 + o], se[k], acc);
        g_tab[v * 3072 + o] = acc;
    }
}

__global__ void prep_mcomb(const float* __restrict__ Wfb)
{
    if (!g_fb_active) return;
    const int k = blockIdx.x;
    __shared__ float sw[128];
    if (threadIdx.x < 128) sw[threadIdx.x] = Wfb[k * 128 + threadIdx.x];
    __syncthreads();
    for (int o = threadIdx.x; o < 3072; o += blockDim.x) {
        float acc = 0.0f;
        #pragma unroll 8
        for (int j = 0; j < 128; ++j) acc = fmaf(g_WihT[j * 3072 + o], sw[j], acc);
        g_McT[k * 3072 + o] = acc;
    }
}

// LN + logits for a finished step: 256 threads (u in [0,256)), named barrier 1.
__device__ __forceinline__ void ln_logits_256(
    int u, const float* __restrict__ gamma, const float* __restrict__ beta,
    const float* sh_rs, float* sh_on, float* sh_red, float* sh_mu, float* sh_rstd, float* scr)
{
    int w8 = u >> 5, l = u & 31;
    float v0 = sh_rs[w8 * 64 + l], v1 = sh_rs[w8 * 64 + 32 + l];
    float sum = v0 + v1, sq = v0 * v0 + v1 * v1;
    #pragma unroll
    for (int off = 16; off; off >>= 1) {
        sum += __shfl_down_sync(0xffffffff, sum, off);
        sq  += __shfl_down_sync(0xffffffff, sq,  off);
    }
    if (l == 0) { sh_red[w8 * 2] = sum; sh_red[w8 * 2 + 1] = sq; }
    asm volatile("bar.sync 1, 256;" ::: "memory");
    if (u < 4) {
        float s = sh_red[4 * u] + sh_red[4 * u + 2];
        float q = sh_red[4 * u + 1] + sh_red[4 * u + 3];
        float mu = s * (1.0f / 128.0f);
        sh_mu[u] = mu;
        sh_rstd[u] = rsqrtf(q * (1.0f / 128.0f) - mu * mu + 1e-5f);
    }
    asm volatile("bar.sync 1, 256;" ::: "memory");
    #pragma unroll
    for (int rep = 0; rep < 2; ++rep) {
        int e = u + rep * 256, n = e >> 7, d = e & 127;
        sh_on[e] = (sh_rs[e] - sh_mu[n]) * sh_rstd[n] * gamma[d] + beta[d];
    }
    asm volatile("bar.sync 1, 256;" ::: "memory");
    {
        int ks = u >> 7, v = u & 127;
        float a0 = 0.0f, a1 = 0.0f;
        if (v < V_) {
            const float* on = sh_on + ks * 256;
            const float* W = g_WrT + (size_t)(ks * 256) * 100 + v;
            #pragma unroll 4
            for (int k = 0; k < 256; k += 2) {
                a0 = fmaf(W[k * 100], on[k], a0);
                a1 = fmaf(W[(k + 1) * 100], on[k + 1], a1);
            }
        }
        scr[u] = a0 + a1;
    }
}

// 128x128 matvec applied to 4 neuron rows with shared weight loads.
// 512 threads: ks = t>>6 (8 K-splits of 16), dp = t&63 (2 outputs).
// Partials -> scr[(ks*4+n)*128 + dp*2 .. +1]
__device__ __forceinline__ void mat128x4(int t, const float* __restrict__ WT,
                                         const float* src, float* scr)
{
    int ks = t >> 6, dp = t & 63;
    const char* wp = (const char*)(WT + (size_t)(ks * 16) * 128 + dp * 2);
    unsigned long long a0 = 0, a1 = 0, a2 = 0, a3 = 0;
    const float* s0 = src + ks * 16;
    #pragma unroll
    for (int k = 0; k < 16; ++k) {
        unsigned long long w = *(const unsigned long long*)(wp + (size_t)k * 512);
        ffma2(a0, w, bcast2(s0[k]));
        ffma2(a1, w, bcast2(s0[128 + k]));
        ffma2(a2, w, bcast2(s0[256 + k]));
        ffma2(a3, w, bcast2(s0[384 + k]));
    }
    *(unsigned long long*)(scr + (ks * 4 + 0) * 128 + dp * 2) = a0;
    *(unsigned long long*)(scr + (ks * 4 + 1) * 128 + dp * 2) = a1;
    *(unsigned long long*)(scr + (ks * 4 + 2) * 128 + dp * 2) = a2;
    *(unsigned long long*)(scr + (ks * 4 + 3) * 128 + dp * 2) = a3;
}

__global__ void __launch_bounds__(1024, 1)
inn_kernel(const int* __restrict__ x,
           const float* __restrict__ b_hh_c, const float* __restrict__ b_op,
           const float* __restrict__ bq, const float* __restrict__ bk, const float* __restrict__ bv,
           const float* __restrict__ bf1, const float* __restrict__ bf2, const float* __restrict__ bwo,
           const float* __restrict__ gamma, const float* __restrict__ beta,
           const float* __restrict__ br,
           float* __restrict__ out, int write_states)
{
    const int b = blockIdx.x;
    const int t = threadIdx.x;

    __shared__ __align__(16) float sh_h[1024];
    __shared__ __align__(16) float scr[6144];
    __shared__ __align__(16) float sh_o[512], sh_q[512], sh_k[512], sh_v[512];
    __shared__ __align__(16) float sh_mx[512], sh_g1[512], sh_pc[512], sh_rs[512], sh_on[512];
    __shared__ __align__(16) float sh_fb[128];
    __shared__ float sh_sc[16], sh_red[16], sh_mu[4], sh_rstd[4];

    sh_h[t] = 0.0f;
    if (t < 128) sh_fb[t] = 0.0f;
    const int fbact = g_fb_active;
    __syncthreads();

    const float inv_sqrt_d = 0.08838834764831845f;
    const int n_t = t >> 8, hi_t = t & 255;

    for (int s = 0; s < S_; ++s) {
        const int tok = __ldg(x + b * S_ + s);
        const float* gr = g_tab + (size_t)tok * 3072 + n_t * 768 + hi_t;
        float gi_r = __ldg(gr), gi_z = __ldg(gr + 256), gi_n = __ldg(gr + 512);
        if (fbact) {
            const float* M = g_McT + n_t * 768 + hi_t;
            for (int k = 0; k < 128; ++k) {
                float f = sh_fb[k];
                gi_r = fmaf(M[k * 3072], f, gi_r);
                gi_z = fmaf(M[k * 3072 + 256], f, gi_z);
                gi_n = fmaf(M[k * 3072 + 512], f, gi_n);
            }
        }

        // ---- Region 1: warps 0-23 Whh matvec; warps 24-31 LN+logits of s-1 ----
        if (t < 768) {
            const int ks = (t >= 384) ? 1 : 0;
            const int grp = t - ks * 384;                       // 4 outputs each
            const float* hrow = sh_h + (2 + (grp >= 192 ? 1 : 0)) * 256 + ks * 128;
            unsigned long long a0 = 0ull, a1 = 0ull;
            if (ks == 0) {
                const unsigned long long* bb = (const unsigned long long*)(b_hh_c + grp * 4);
                a0 = bb[0]; a1 = bb[1];
            }
            const char* wp = (const char*)(g_WhhT + (size_t)(ks * 128) * 1536 + grp * 4);
            #pragma unroll 4
            for (int k = 0; k < 128; ++k) {
                ulonglong2 w = *(const ulonglong2*)(wp + (size_t)k * 6144);
                unsigned long long xx = bcast2(hrow[k]);
                ffma2(a0, w.x, xx); ffma2(a1, w.y, xx);
            }
            ulonglong2 st2; st2.x = a0; st2.y = a1;
            *(ulonglong2*)(scr + 2048 + ks * 1536 + grp * 4) = st2;
        } else if (s > 0) {
            ln_logits_256(t - 768, gamma, beta, sh_rs, sh_on, sh_red, sh_mu, sh_rstd, scr);
        }
        __syncthreads();

        // ---- GRU update (+ store logits of s-1) ----
        {
            float h_old = sh_h[t];
            float ghr, ghz, ghn;
            if (n_t < 2) { ghr = 0.0f; ghz = 5.0f; ghn = h_old; }
            else {
                const float* P = scr + 2048 + (n_t - 2) * 768 + hi_t;
                ghr = P[0]   + P[1536];
                ghz = P[256] + P[1536 + 256];
                ghn = P[512] + P[1536 + 512];
            }
            float rg = sigf(gi_r + ghr);
            float zg = sigf(gi_z + ghz);
            float ng = tanhf(fmaf(rg, ghn, gi_n));
            sh_h[t] = (1.0f - zg) * ng + zg * h_old;
            if (s > 0 && t < V_)
                out[(size_t)b * S_ * V_ + (size_t)(s - 1) * V_ + t] = scr[t] + scr[128 + t] + br[t];
        }
        __syncthreads();

        // ---- o = W_op @ h + b_op : 1024 threads = 4 K-splits x 256 pairs ----
        {
            int ks = t >> 8, g = t & 255;
            const float* hrow = sh_h + (g >> 6) * 256 + ks * 64;
            const char* wp = (const char*)(g_WopT + (size_t)(ks * 64) * 512 + g * 2);
            unsigned long long acc = 0ull;
            #pragma unroll 4
            for (int k = 0; k < 64; ++k)
                ffma2(acc, *(const unsigned long long*)(wp + (size_t)k * 2048), bcast2(hrow[k]));
            *(unsigned long long*)(scr + ks * 512 + g * 2) = acc;
        }
        __syncthreads();
        if (t < 512) sh_o[t] = scr[t] + scr[512 + t] + scr[1024 + t] + scr[1536 + t] + b_op[t];
        __syncthreads();

        // ---- q,k,v: 768 threads = 3 mats x 4 K-splits x 64 pairs, weights shared over 4 neurons ----
        if (t < 768) {
            int mat = t >> 8, r = t & 255, ks = r >> 6, dp = r & 63;
            const float* WT = (mat == 0) ? g_WqT : (mat == 1) ? g_WkT : g_WvT;
            const char* wp = (const char*)(WT + (size_t)(ks * 32) * 128 + dp * 2);
            unsigned long long a0 = 0, a1 = 0, a2 = 0, a3 = 0;
            const float* s0 = sh_o + ks * 32;
            #pragma unroll 4
            for (int k = 0; k < 32; ++k) {
                unsigned long long w = *(const unsigned long long*)(wp + (size_t)k * 512);
                ffma2(a0, w, bcast2(s0[k]));
                ffma2(a1, w, bcast2(s0[128 + k]));
                ffma2(a2, w, bcast2(s0[256 + k]));
                ffma2(a3, w, bcast2(s0[384 + k]));
            }
            float* base = scr + (size_t)(mat * 4 + ks) * 512 + dp * 2;
            *(unsigned long long*)(base)       = a0;
            *(unsigned long long*)(base + 128) = a1;
            *(unsigned long long*)(base + 256) = a2;
            *(unsigned long long*)(base + 384) = a3;
        }
        __syncthreads();
        for (int u = t; u < 1536; u += 1024) {
            int mat = u >> 9, g = u & 511, d = g & 127;
            const float* pb = scr + (size_t)(mat * 4) * 512 + g;
            float bias = (mat == 0) ? bq[d] : (mat == 1) ? bk[d] : bv[d];
            float val = pb[0] + pb[512] + pb[1024] + pb[1536] + bias;
            ((mat == 0) ? sh_q : (mat == 1) ? sh_k : sh_v)[g] = val;
        }
        __syncthreads();

        // ---- attention scores + softmax + mix ----
        if (t < 512) {
            int w = t >> 5, l = t & 31, n = w >> 2, m = w & 3;
            float sum = sh_q[n * 128 + l]      * sh_k[m * 128 + l]
                      + sh_q[n * 128 + 32 + l] * sh_k[m * 128 + 32 + l]
                      + sh_q[n * 128 + 64 + l] * sh_k[m * 128 + 64 + l]
                      + sh_q[n * 128 + 96 + l] * sh_k[m * 128 + 96 + l];
            #pragma unroll
            for (int off = 16; off; off >>= 1) sum += __shfl_down_sync(0xffffffff, sum, off);
            if (l == 0) sh_sc[n * 4 + m] = sum * inv_sqrt_d;
        }
        __syncthreads();
        if (t < 4) {
            float s0 = sh_sc[t * 4], s1 = sh_sc[t * 4 + 1], s2 = sh_sc[t * 4 + 2], s3 = sh_sc[t * 4 + 3];
            float mx = fmaxf(fmaxf(s0, s1), fmaxf(s2, s3));
            float e0 = expf(s0 - mx), e1 = expf(s1 - mx), e2 = expf(s2 - mx), e3 = expf(s3 - mx);
            float den = 1.0f / (e0 + e1 + e2 + e3);
            sh_sc[t * 4] = e0 * den; sh_sc[t * 4 + 1] = e1 * den;
            sh_sc[t * 4 + 2] = e2 * den; sh_sc[t * 4 + 3] = e3 * den;
        }
        __syncthreads();
        if (t < 512) {
            int n = t >> 7, d = t & 127;
            sh_mx[t] = sh_sc[n * 4] * sh_v[d] + sh_sc[n * 4 + 1] * sh_v[128 + d]
                     + sh_sc[n * 4 + 2] * sh_v[256 + d] + sh_sc[n * 4 + 3] * sh_v[384 + d];
        }
        __syncthreads();

        // ---- f1 + GELU ----
        if (t < 512) mat128x4(t, g_Wf1T, sh_mx, scr);
        __syncthreads();
        if (t < 512) {
            int n = t >> 7, d = t & 127;
            float a = 0.0f;
            #pragma unroll
            for (int ks = 0; ks < 8; ++ks) a += scr[(ks * 4 + n) * 128 + d];
            sh_g1[t] = geluf(a + bf1[d]);
        }
        __syncthreads();

        // ---- f2 ----
        if (t < 512) mat128x4(t, g_Wf2T, sh_g1, scr);
        __syncthreads();
        if (t < 512) {
            int n = t >> 7, d = t & 127;
            float a = 0.0f;
            #pragma unroll
            for (int ks = 0; ks < 8; ++ks) a += scr[(ks * 4 + n) * 128 + d];
            sh_pc[t] = a + bf2[d];
        }
        __syncthreads();

        // ---- res = o + proc@Wwo^T + bwo ; fb = mean_n proc ----
        if (t < 512) mat128x4(t, g_WwoT, sh_pc, scr);
        __syncthreads();
        if (t < 512) {
            int n = t >> 7, d = t & 127;
            float a = 0.0f;
            #pragma unroll
            for (int ks = 0; ks < 8; ++ks) a += scr[(ks * 4 + n) * 128 + d];
            sh_rs[t] = sh_o[t] + a + bwo[d];
        }
        if (t < 128)
            sh_fb[t] = 0.25f * (sh_pc[t] + sh_pc[128 + t] + sh_pc[256 + t] + sh_pc[384 + t]);
        __syncthreads();
    }

    // ---- final step's LN + logits ----
    if (t >= 768)
        ln_logits_256(t - 768, gamma, beta, sh_rs, sh_on, sh_red, sh_mu, sh_rstd, scr);
    __syncthreads();
    if (t < V_)
        out[(size_t)b * S_ * V_ + (size_t)(S_ - 1) * V_ + t] = scr[t] + scr[128 + t] + br[t];

    if (write_states) {
        size_t OFF1 = (size_t)B_ * S_ * V_;
        out[OFF1 + (size_t)n_t * B_ * H_ + (size_t)b * H_ + hi_t] = sh_h[t];
        if (t < 128)
            out[OFF1 + (size_t)N_ * B_ * H_ + (size_t)b * D_ + t] = sh_fb[t];
    }
}

extern "C" void kernel_launch(void* const* d_in, const int* in_sizes, int n_in,
                              void* d_out, int out_size)
{
    const int*   x      = (const int*)  d_in[0];
    const float* emb    = (const float*)d_in[1];
    const float* W_ih   = (const float*)d_in[2];
    const float* b_ih   = (const float*)d_in[3];
    const float* W_hh_c = (const float*)d_in[4];
    const float* b_hh_c = (const float*)d_in[5];
    const float* W_op   = (const float*)d_in[6];
    const float* b_op   = (const float*)d_in[7];
    const float* Wq     = (const float*)d_in[8];
    const float* bq     = (const float*)d_in[9];
    const float* Wk     = (const float*)d_in[10];
    const float* bk     = (const float*)d_in[11];
    const float* Wv     = (const float*)d_in[12];
    const float* bv     = (const float*)d_in[13];
    const float* Wf1    = (const float*)d_in[14];
    const float* bf1    = (const float*)d_in[15];
    const float* Wf2    = (const float*)d_in[16];
    const float* bf2    = (const float*)d_in[17];
    const float* Wwo    = (const float*)d_in[18];
    const float* bwo    = (const float*)d_in[19];
    const float* gamma  = (const float*)d_in[20];
    const float* beta   = (const float*)d_in[21];
    const float* Wr     = (const float*)d_in[22];
    const float* br     = (const float*)d_in[23];
    const float* Wfb    = (const float*)d_in[24];
    const float* bfb    = (const float*)d_in[25];
    float* out = (float*)d_out;

    prep_reset<<<1, 1>>>();
    prep_transpose<<<512, 256>>>(W_ih, W_hh_c, W_op, Wq, Wk, Wv, Wf1, Wf2, Wwo, Wr, Wfb, bfb);
    prep_tab<<<100, 256>>>(emb, b_ih, bfb);
    prep_mcomb<<<128, 256>>>(Wfb);

    long long FULL = (long long)B_ * S_ * V_ + (long long)N_ * B_ * H_ + (long long)B_ * D_;
    int write_states = ((long long)out_size >= FULL) ? 1 : 0;

    inn_kernel<<<B_, 1024>>>(x, b_hh_c, b_op, bq, bk, bv, bf1, bf2, bwo,
                             gamma, beta, br, out, write_states);
}